// round 4
// baseline (speedup 1.0000x reference)
#include <cuda_runtime.h>

#define IN_CH 16
#define OUT_CH 64
#define HDIM 32
#define WDIM 32
#define NB 8
#define KHW 9
#define F (IN_CH * KHW)      // 144
#define OCG 8                // out channels per block
#define ROWS 4               // output rows per block
#define NCP 16               // column pairs (2 cols per thread)
#define CSPLIT 4             // input-channel split
#define CPT (IN_CH / CSPLIT) // 4 channels per thread
#define TPB 256              // 16 cp * 4 rows * 4 csplit
#define WPAD 36              // padded row stride (mult of 4)

__global__ __launch_bounds__(TPB) void normdist_kernel(
    const float* __restrict__ x,      // (8,16,32,32)
    const float* __restrict__ weight, // (64,144)
    const float* __restrict__ bias,   // (64)
    float* __restrict__ out)          // (8,64,32,32)
{
    const int og  = blockIdx.x;            // 0..7 out-channel group
    const int rg  = blockIdx.y;            // 0..7 row group
    const int n   = blockIdx.z;            // 0..7 batch
    const int tid = threadIdx.x;
    const int cp  = tid & 15;              // 0..15 column pair
    const int r   = (tid >> 4) & 3;        // 0..3 row
    const int cs  = tid >> 6;              // 0..3 channel quarter

    const int row0 = rg * ROWS;

    __shared__ float xs[IN_CH][ROWS + 2][WPAD];            // 13824 B
    __shared__ __align__(16) float wT[F][OCG];             // 4608 B
    __shared__ float ps[CSPLIT - 1][ROWS][NCP][18];        // 13824 B partial maxes

    // ---- transposed weights: wT[f][oo] = weight[(og*8+oo)*144 + f]
    for (int idx = tid; idx < F * OCG; idx += TPB) {
        int oo = idx & (OCG - 1);
        int f  = idx >> 3;
        wT[f][oo] = weight[(og * OCG + oo) * F + f];
    }

    // ---- x tile with halo, zero padded, row stride WPAD
    const float* xn = x + (size_t)n * IN_CH * HDIM * WDIM;
    const int tile_elems = IN_CH * (ROWS + 2) * WPAD;      // 3456
    for (int idx = tid; idx < tile_elems; idx += TPB) {
        int c   = idx / ((ROWS + 2) * WPAD);
        int rem = idx % ((ROWS + 2) * WPAD);
        int rr  = rem / WPAD;
        int cc  = rem % WPAD;
        int gr  = row0 - 1 + rr;
        int gc  = cc - 1;
        float v = 0.0f;
        if (gr >= 0 && gr < HDIM && gc >= 0 && gc < WDIM && cc < WDIM + 2)
            v = xn[(c * HDIM + gr) * WDIM + gc];
        xs[c][rr][cc] = v;
    }
    __syncthreads();

    float accA[OCG], accB[OCG];
    #pragma unroll
    for (int o = 0; o < OCG; o++) { accA[o] = 0.0f; accB[o] = 0.0f; }

    // per-thread bases; all further offsets are compile-time constants
    const float* xbase = &xs[cs * CPT][r][2 * cp];
    const float* wbase = &wT[cs * CPT * KHW][0];

    #pragma unroll
    for (int ci = 0; ci < CPT; ci++) {
        // 3 rows x 4 cols patch segment: cc in [2cp, 2cp+4)
        float v[3][4];
        #pragma unroll
        for (int i = 0; i < 3; i++) {
            const float2* row = reinterpret_cast<const float2*>(
                xbase + ci * (ROWS + 2) * WPAD + i * WPAD);
            float2 a = row[0];
            float2 b = row[1];
            v[i][0] = a.x; v[i][1] = a.y; v[i][2] = b.x; v[i][3] = b.y;
        }

        #pragma unroll
        for (int i = 0; i < 3; i++) {
            #pragma unroll
            for (int j = 0; j < 3; j++) {
                const float4* w4 = reinterpret_cast<const float4*>(
                    wbase + (ci * KHW + i * 3 + j) * OCG);
                float4 wa = w4[0], wb = w4[1];
                const float pA = v[i][j];
                const float pB = v[i][j + 1];
                accA[0] = fmaxf(accA[0], fabsf(pA - wa.x));
                accA[1] = fmaxf(accA[1], fabsf(pA - wa.y));
                accA[2] = fmaxf(accA[2], fabsf(pA - wa.z));
                accA[3] = fmaxf(accA[3], fabsf(pA - wa.w));
                accA[4] = fmaxf(accA[4], fabsf(pA - wb.x));
                accA[5] = fmaxf(accA[5], fabsf(pA - wb.y));
                accA[6] = fmaxf(accA[6], fabsf(pA - wb.z));
                accA[7] = fmaxf(accA[7], fabsf(pA - wb.w));
                accB[0] = fmaxf(accB[0], fabsf(pB - wa.x));
                accB[1] = fmaxf(accB[1], fabsf(pB - wa.y));
                accB[2] = fmaxf(accB[2], fabsf(pB - wa.z));
                accB[3] = fmaxf(accB[3], fabsf(pB - wa.w));
                accB[4] = fmaxf(accB[4], fabsf(pB - wb.x));
                accB[5] = fmaxf(accB[5], fabsf(pB - wb.y));
                accB[6] = fmaxf(accB[6], fabsf(pB - wb.z));
                accB[7] = fmaxf(accB[7], fabsf(pB - wb.w));
            }
        }
    }

    // ---- reduce the 4 channel-quarters
    if (cs > 0) {
        float* p = &ps[cs - 1][r][cp][0];
        #pragma unroll
        for (int o = 0; o < OCG; o++) { p[o] = accA[o]; p[OCG + o] = accB[o]; }
    }
    __syncthreads();

    if (cs == 0) {
        const int orow = row0 + r;
        float* outp = out + (((size_t)n * OUT_CH + og * OCG) * HDIM + orow) * WDIM + 2 * cp;
        #pragma unroll
        for (int o = 0; o < OCG; o++) {
            float a = accA[o], b = accB[o];
            #pragma unroll
            for (int q = 0; q < CSPLIT - 1; q++) {
                a = fmaxf(a, ps[q][r][cp][o]);
                b = fmaxf(b, ps[q][r][cp][OCG + o]);
            }
            const float bi = __ldg(&bias[og * OCG + o]);
            float2 res = make_float2(a + bi, b + bi);
            *reinterpret_cast<float2*>(outp + (size_t)o * HDIM * WDIM) = res;
        }
    }
}

extern "C" void kernel_launch(void* const* d_in, const int* in_sizes, int n_in,
                              void* d_out, int out_size) {
    const float* x      = (const float*)d_in[0];
    const float* weight = (const float*)d_in[1];
    const float* bias   = (const float*)d_in[2];
    float* out          = (float*)d_out;

    dim3 grid(OUT_CH / OCG, HDIM / ROWS, NB);   // (8, 8, 8) = 512 blocks
    normdist_kernel<<<grid, TPB>>>(x, weight, bias, out);
}

// round 6
// speedup vs baseline: 1.0681x; 1.0681x over previous
#include <cuda_runtime.h>

#define IN_CH 16
#define OUT_CH 64
#define HDIM 32
#define WDIM 32
#define NB 8
#define KHW 9
#define F (IN_CH * KHW)      // 144
#define OCG 8                // out channels per block
#define ROWS 2               // output rows per block
#define CSPLIT 4             // input-channel split within block
#define CPT (IN_CH / CSPLIT) // 4 channels per thread
#define TPB 256              // 32 cols * 2 rows * 4 csplit
#define TW 34                // tile width with halo

__global__ __launch_bounds__(TPB, 7) void normdist_kernel(
    const float* __restrict__ x,      // (8,16,32,32)
    const float* __restrict__ weight, // (64,144)
    const float* __restrict__ bias,   // (64)
    float* __restrict__ out)          // (8,64,32,32)
{
    const int og   = blockIdx.x;           // 0..7 out-channel group (8 ch)
    const int rg   = blockIdx.y;           // 0..15 row group (2 rows)
    const int n    = blockIdx.z;           // 0..7 batch
    const int tid  = threadIdx.x;
    const int cpos = tid & 31;             // 0..31 col
    const int r    = (tid >> 5) & 1;       // 0..1 row
    const int cs   = tid >> 6;             // 0..3 channel quarter

    const int row0 = rg * ROWS;

    __shared__ float xs[IN_CH][ROWS + 2][TW];             // 16*4*34*4 = 8704 B
    __shared__ __align__(16) float wT[F][OCG];            // 4608 B
    __shared__ float ps[CSPLIT - 1][ROWS][32][OCG + 1];   // 3*2*32*9*4 = 6912 B

    // ---- transposed weights: wT[f][oo] = weight[(og*8+oo)*144 + f]
    for (int idx = tid; idx < F * OCG; idx += TPB) {
        int oo = idx & (OCG - 1);
        int f  = idx >> 3;
        wT[f][oo] = weight[(og * OCG + oo) * F + f];
    }

    // ---- x tile with halo (zero padding)
    const float* xn = x + (size_t)n * IN_CH * HDIM * WDIM;
    const int tile_elems = IN_CH * (ROWS + 2) * TW;       // 2176
    for (int idx = tid; idx < tile_elems; idx += TPB) {
        int c   = idx / ((ROWS + 2) * TW);
        int rem = idx % ((ROWS + 2) * TW);
        int rr  = rem / TW;
        int cc  = rem % TW;
        int gr  = row0 - 1 + rr;
        int gc  = cc - 1;
        float v = 0.0f;
        if (gr >= 0 && gr < HDIM && gc >= 0 && gc < WDIM)
            v = xn[(c * HDIM + gr) * WDIM + gc];
        xs[c][rr][cc] = v;
    }
    __syncthreads();

    float acc[OCG];
    #pragma unroll
    for (int o = 0; o < OCG; o++) acc[o] = 0.0f;   // |.| >= 0

    const float* xbase = &xs[cs * CPT][r][cpos];
    const float* wbase = &wT[cs * CPT * KHW][0];

    #pragma unroll
    for (int ci = 0; ci < CPT; ci++) {
        // 3x3 patch into registers (compile-time offsets from xbase)
        float p[KHW];
        #pragma unroll
        for (int i = 0; i < 3; i++)
            #pragma unroll
            for (int j = 0; j < 3; j++)
                p[i * 3 + j] = xbase[ci * (ROWS + 2) * TW + i * TW + j];

        #pragma unroll
        for (int t = 0; t < KHW; t++) {
            const float4* w4 = reinterpret_cast<const float4*>(
                wbase + (ci * KHW + t) * OCG);
            float4 wa = w4[0], wb = w4[1];   // 2x LDS.128 broadcast
            const float pj = p[t];
            acc[0] = fmaxf(acc[0], fabsf(pj - wa.x));
            acc[1] = fmaxf(acc[1], fabsf(pj - wa.y));
            acc[2] = fmaxf(acc[2], fabsf(pj - wa.z));
            acc[3] = fmaxf(acc[3], fabsf(pj - wa.w));
            acc[4] = fmaxf(acc[4], fabsf(pj - wb.x));
            acc[5] = fmaxf(acc[5], fabsf(pj - wb.y));
            acc[6] = fmaxf(acc[6], fabsf(pj - wb.z));
            acc[7] = fmaxf(acc[7], fabsf(pj - wb.w));
        }
    }

    // ---- reduce the 4 channel-quarters
    if (cs > 0) {
        float* p = &ps[cs - 1][r][cpos][0];
        #pragma unroll
        for (int o = 0; o < OCG; o++) p[o] = acc[o];
    }
    __syncthreads();

    if (cs == 0) {
        const int orow = row0 + r;
        float* outp = out + (((size_t)n * OUT_CH + og * OCG) * HDIM + orow) * WDIM + cpos;
        #pragma unroll
        for (int o = 0; o < OCG; o++) {
            float v = acc[o];
            #pragma unroll
            for (int q = 0; q < CSPLIT - 1; q++)
                v = fmaxf(v, ps[q][r][cpos][o]);
            outp[(size_t)o * HDIM * WDIM] = v + __ldg(&bias[og * OCG + o]);
        }
    }
}

extern "C" void kernel_launch(void* const* d_in, const int* in_sizes, int n_in,
                              void* d_out, int out_size) {
    const float* x      = (const float*)d_in[0];
    const float* weight = (const float*)d_in[1];
    const float* bias   = (const float*)d_in[2];
    float* out          = (float*)d_out;

    dim3 grid(OUT_CH / OCG, HDIM / ROWS, NB);   // (8, 16, 8) = 1024 blocks
    normdist_kernel<<<grid, TPB>>>(x, weight, bias, out);
}

// round 7
// speedup vs baseline: 1.1970x; 1.1208x over previous
#include <cuda_runtime.h>

#define IN_CH 16
#define OUT_CH 64
#define HDIM 32
#define WDIM 32
#define NB 8
#define KHW 9
#define F (IN_CH * KHW)      // 144
#define OCG 8                // out channels per block
#define ROWS 2               // output rows per block
#define CSPLIT 4             // input-channel split within block
#define CPT (IN_CH / CSPLIT) // 4 channels per thread
#define TPB 256              // 32 cols * 2 rows * 4 csplit
#define TW 34                // tile width with halo

__global__ __launch_bounds__(TPB, 6) void normdist_kernel(
    const float* __restrict__ x,      // (8,16,32,32)
    const float* __restrict__ weight, // (64,144)
    const float* __restrict__ bias,   // (64)
    float* __restrict__ out)          // (8,64,32,32)
{
    const int og   = blockIdx.x;           // 0..7 out-channel group (8 ch)
    const int rg   = blockIdx.y;           // 0..15 row group (2 rows)
    const int n    = blockIdx.z;           // 0..7 batch
    const int tid  = threadIdx.x;
    const int cpos = tid & 31;             // 0..31 col
    const int r    = (tid >> 5) & 1;       // 0..1 row
    const int cs   = tid >> 6;             // 0..3 channel quarter

    const int row0 = rg * ROWS;

    __shared__ float xs[IN_CH][ROWS + 2][TW];             // 8704 B
    __shared__ __align__(16) float wT[F][OCG];            // 4608 B
    __shared__ float ps[CSPLIT - 1][ROWS][32][OCG + 1];   // 6912 B

    // ---- transposed weights: wT[f][oo] = weight[(og*8+oo)*144 + f]
    {
        const float* wsrc = weight + og * OCG * F;
        #pragma unroll
        for (int k = 0; k < 5; k++) {            // ceil(1152/256) iterations
            int idx = tid + k * TPB;
            if (idx < F * OCG) {
                int oo = idx & (OCG - 1);
                int f  = idx >> 3;
                wT[f][oo] = wsrc[oo * F + f];
            }
        }
    }

    // ---- x tile with halo (zero padding); shift-only indexing.
    // 64 (channel,row) pairs, 4 lanes each sweep the 34 columns.
    {
        const float* xn = x + (size_t)n * IN_CH * HDIM * WDIM;
        const int pair = tid >> 2;             // 0..63 = c*4 + rr
        const int l4   = tid & 3;
        const int c    = pair >> 2;            // 0..15
        const int rr   = pair & 3;             // 0..3
        const int gr   = row0 - 1 + rr;
        const bool rok = (gr >= 0) && (gr < HDIM);
        const float* src = xn + (c * HDIM + gr) * WDIM;
        float* dst = &xs[c][rr][0];
        #pragma unroll
        for (int e = 0; e < 9; e++) {          // 9*4=36 >= 34
            int cc = l4 + e * 4;
            if (cc < TW) {
                int gc = cc - 1;
                float v = 0.0f;
                if (rok && gc >= 0 && gc < WDIM) v = src[gc];
                dst[cc] = v;
            }
        }
    }
    __syncthreads();

    float acc[OCG];
    #pragma unroll
    for (int o = 0; o < OCG; o++) acc[o] = 0.0f;   // |.| >= 0

    const float* xbase = &xs[cs * CPT][r][cpos];
    const float* wbase = &wT[cs * CPT * KHW][0];

    #pragma unroll
    for (int ci = 0; ci < CPT; ci++) {
        // 3x3 patch into registers (compile-time offsets from xbase)
        float p[KHW];
        #pragma unroll
        for (int i = 0; i < 3; i++)
            #pragma unroll
            for (int j = 0; j < 3; j++)
                p[i * 3 + j] = xbase[ci * (ROWS + 2) * TW + i * TW + j];

        #pragma unroll
        for (int t = 0; t < KHW; t++) {
            const float4* w4 = reinterpret_cast<const float4*>(
                wbase + (ci * KHW + t) * OCG);
            float4 wa = w4[0], wb = w4[1];   // 2x LDS.128 broadcast
            const float pj = p[t];
            acc[0] = fmaxf(acc[0], fabsf(pj - wa.x));
            acc[1] = fmaxf(acc[1], fabsf(pj - wa.y));
            acc[2] = fmaxf(acc[2], fabsf(pj - wa.z));
            acc[3] = fmaxf(acc[3], fabsf(pj - wa.w));
            acc[4] = fmaxf(acc[4], fabsf(pj - wb.x));
            acc[5] = fmaxf(acc[5], fabsf(pj - wb.y));
            acc[6] = fmaxf(acc[6], fabsf(pj - wb.z));
            acc[7] = fmaxf(acc[7], fabsf(pj - wb.w));
        }
    }

    // ---- reduce the 4 channel-quarters
    if (cs > 0) {
        float* p = &ps[cs - 1][r][cpos][0];
        #pragma unroll
        for (int o = 0; o < OCG; o++) p[o] = acc[o];
    }
    __syncthreads();

    if (cs == 0) {
        const int orow = row0 + r;
        float* outp = out + (((size_t)n * OUT_CH + og * OCG) * HDIM + orow) * WDIM + cpos;
        #pragma unroll
        for (int o = 0; o < OCG; o++) {
            float v = acc[o];
            #pragma unroll
            for (int q = 0; q < CSPLIT - 1; q++)
                v = fmaxf(v, ps[q][r][cpos][o]);
            outp[(size_t)o * HDIM * WDIM] = v + __ldg(&bias[og * OCG + o]);
        }
    }
}

extern "C" void kernel_launch(void* const* d_in, const int* in_sizes, int n_in,
                              void* d_out, int out_size) {
    const float* x      = (const float*)d_in[0];
    const float* weight = (const float*)d_in[1];
    const float* bias   = (const float*)d_in[2];
    float* out          = (float*)d_out;

    dim3 grid(OUT_CH / OCG, HDIM / ROWS, NB);   // (8, 16, 8) = 1024 blocks
    normdist_kernel<<<grid, TPB>>>(x, weight, bias, out);
}